// round 10
// baseline (speedup 1.0000x reference)
#include <cuda_runtime.h>
#include <cstdint>

constexpr int B = 16384;
constexpr int F = 50;
constexpr int K = 64;
constexpr int TPR = 16;              // threads per row: each owns 4 k's (one float4)
constexpr int RPB = 16;              // rows per block: 16 x 16 = 256 threads
constexpr int CH  = 10;              // load batch: 10 in-flight LDG.128 per thread

__global__ __launch_bounds__(RPB * TPR)
void fm2_kernel(const float* __restrict__ vals,  // [B, F]
                const int*   __restrict__ idx,   // [B, F] int32
                const float* __restrict__ emb,   // [1e6, K] f32
                float* __restrict__ out)         // [B, K] f32
{
    const int tid   = threadIdx.x;
    const int r_blk = tid >> 4;                  // 0..15
    const int kq    = tid & (TPR - 1);           // float4 column 0..15
    const int row   = blockIdx.x * RPB + r_blk;

    __shared__ float sv[RPB][F];
    __shared__ int   soff[RPB][F];               // float4-element offset = idx * 16

    for (int i = tid; i < RPB * F; i += RPB * TPR) {
        const int r = i / F;
        const int f = i - r * F;
        const int g = (blockIdx.x * RPB + r) * F + f;
        sv[r][f]   = vals[g];
        soff[r][f] = idx[g] * (K / 4);           // index into float4-view of emb
    }
    __syncthreads();

    const float4* __restrict__ emb4 = (const float4*)emb;

    float s1x = 0.f, s1y = 0.f, s1z = 0.f, s1w = 0.f;
    float s2x = 0.f, s2y = 0.f, s2z = 0.f, s2w = 0.f;

#pragma unroll
    for (int c = 0; c < F; c += CH) {            // 5 chunks of 10
        // Phase 1: read offsets, then issue all CH gathers back-to-back
        int  o[CH];
#pragma unroll
        for (int j = 0; j < CH; ++j) o[j] = soff[r_blk][c + j];

        float4 e[CH];
#pragma unroll
        for (int j = 0; j < CH; ++j) e[j] = __ldg(&emb4[o[j] + kq]);

        // Phase 2: accumulate
#pragma unroll
        for (int j = 0; j < CH; ++j) {
            const float v = sv[r_blk][c + j];
            const float ax = v * e[j].x, ay = v * e[j].y;
            const float az = v * e[j].z, aw = v * e[j].w;
            s1x += ax;      s1y += ay;      s1z += az;      s1w += aw;
            s2x += ax * ax; s2y += ay * ay; s2z += az * az; s2w += aw * aw;
        }
    }

    float4 res;
    res.x = s1x * s1x - s2x;
    res.y = s1y * s1y - s2y;
    res.z = s1z * s1z - s2z;
    res.w = s1w * s1w - s2w;
    ((float4*)out)[row * TPR + kq] = res;
}

extern "C" void kernel_launch(void* const* d_in, const int* in_sizes, int n_in,
                              void* d_out, int out_size)
{
    const float* vals = (const float*)d_in[0];
    const int*   idx  = (const int*)d_in[1];
    const float* emb  = (const float*)d_in[2];
    float*       out  = (float*)d_out;

    fm2_kernel<<<B / RPB, RPB * TPR>>>(vals, idx, emb, out);
}

// round 11
// speedup vs baseline: 1.0197x; 1.0197x over previous
#include <cuda_runtime.h>
#include <cstdint>

constexpr int B = 16384;
constexpr int F = 50;
constexpr int K = 64;
constexpr int TPR = 16;              // threads per row: each owns 4 k's (one float4)
constexpr int RPB = 16;              // rows per block: 16 x 16 = 256 threads
constexpr int CH  = 10;              // load batch: 10 in-flight LDG.128 per thread

__global__
void fm2_kernel(const float* __restrict__ vals,  // [B, F]
                const int*   __restrict__ idx,   // [B, F] int32
                const float* __restrict__ emb,   // [1e6, K] f32
                float* __restrict__ out)         // [B, K] f32
{
    const int tid   = threadIdx.x;
    const int r_blk = tid >> 4;                  // 0..15
    const int kq    = tid & (TPR - 1);           // float4 column 0..15
    const int row   = blockIdx.x * RPB + r_blk;

    __shared__ float sv[RPB][F];
    __shared__ int   soff[RPB][F];               // float4-element offset = idx * 16

    for (int i = tid; i < RPB * F; i += RPB * TPR) {
        const int r = i / F;
        const int f = i - r * F;
        const int g = (blockIdx.x * RPB + r) * F + f;
        sv[r][f]   = vals[g];
        soff[r][f] = idx[g] * (K / 4);           // index into float4-view of emb
    }
    __syncthreads();

    const float4* __restrict__ emb4 = (const float4*)emb;

    float s1x = 0.f, s1y = 0.f, s1z = 0.f, s1w = 0.f;
    float s2x = 0.f, s2y = 0.f, s2z = 0.f, s2w = 0.f;

#pragma unroll
    for (int c = 0; c < F; c += CH) {            // 5 chunks of 10
        // Phase 0: addresses
        const float4* p[CH];
#pragma unroll
        for (int j = 0; j < CH; ++j) p[j] = emb4 + soff[r_blk][c + j] + kq;

        // Phase 1: force-batched vector gathers. All outputs stay live until
        // phase 2, so ptxas must hold CH float4s (~40 regs) in flight.
        float ex[CH], ey[CH], ez[CH], ew[CH];
#pragma unroll
        for (int j = 0; j < CH; ++j) {
            asm("ld.global.nc.v4.f32 {%0,%1,%2,%3}, [%4];"
                : "=f"(ex[j]), "=f"(ey[j]), "=f"(ez[j]), "=f"(ew[j])
                : "l"(p[j]));
        }

        // Phase 2: accumulate
#pragma unroll
        for (int j = 0; j < CH; ++j) {
            const float v = sv[r_blk][c + j];
            const float ax = v * ex[j], ay = v * ey[j];
            const float az = v * ez[j], aw = v * ew[j];
            s1x += ax;      s1y += ay;      s1z += az;      s1w += aw;
            s2x += ax * ax; s2y += ay * ay; s2z += az * az; s2w += aw * aw;
        }
    }

    float4 res;
    res.x = s1x * s1x - s2x;
    res.y = s1y * s1y - s2y;
    res.z = s1z * s1z - s2z;
    res.w = s1w * s1w - s2w;
    ((float4*)out)[row * TPR + kq] = res;
}

extern "C" void kernel_launch(void* const* d_in, const int* in_sizes, int n_in,
                              void* d_out, int out_size)
{
    const float* vals = (const float*)d_in[0];
    const int*   idx  = (const int*)d_in[1];
    const float* emb  = (const float*)d_in[2];
    float*       out  = (float*)d_out;

    fm2_kernel<<<B / RPB, RPB * TPR>>>(vals, idx, emb, out);
}